// round 7
// baseline (speedup 1.0000x reference)
#include <cuda_runtime.h>
#include <math.h>

#define T_   8192
#define DIN  2048
#define D_   512
#define H_   512
#define H3_  1536
#define A_   18

#define NC   64          // recurrence CTAs (single wave: 64 < 148 SMs)
#define HC   (H_/NC)     // 8 hidden units per CTA (one warp each)
#define EPAD 16          // u64 per element slot: 128B = one L2 line per element

// ---------------- scratch (device globals: no allocation allowed) ----------
__device__ float g_z1[(size_t)T_ * D_];          // 16 MB
__device__ float g_z2[(size_t)T_ * D_];          // 16 MB
__device__ float g_X [(size_t)T_ * H3_];         // 48 MB
__device__ float g_seq[(size_t)T_ * H_];         // 16 MB
// tagged, double-buffered h; each element on its OWN 128B line so the
// producer's store never queues behind the poll storm of other elements.
__device__ __align__(128) unsigned long long g_hbuf[2][H_][EPAD];   // 128 KB

// ---------------- relaxed gpu-scope 64-bit ld/st for the spin protocol -----
__device__ __forceinline__ unsigned long long ld_relaxed_u64(const unsigned long long* p) {
    unsigned long long v;
    asm volatile("ld.relaxed.gpu.global.u64 %0, [%1];" : "=l"(v) : "l"(p) : "memory");
    return v;
}
__device__ __forceinline__ void st_relaxed_u64(unsigned long long* p, unsigned long long v) {
    asm volatile("st.relaxed.gpu.global.u64 [%0], %1;" :: "l"(p), "l"(v) : "memory");
}

// ---------------- fp32 tiled GEMM: C = act(A[M,K] @ B[K,N] + bias) ---------
// doInit: block (0,0) additionally resets the tagged h buffer.
__global__ __launch_bounds__(256) void gemm_kernel(
    const float* __restrict__ A, const float* __restrict__ B,
    const float* __restrict__ bias, float* __restrict__ C,
    int M, int N, int K, int doRelu,
    const float* __restrict__ h0, int doInit)
{
    __shared__ float As[16][64];
    __shared__ float Bs[16][64];
    const int tid = threadIdx.x;

    if (doInit && blockIdx.x == 0 && blockIdx.y == 0) {
        // parity 0: sentinel; parity 1: h_{-1} tagged 0 (step 0 polls parity 1)
#pragma unroll
        for (int k = 0; k < 4; k++) {
            int idx = tid + k * 256;          // 0..1023
            int par = idx >> 9;
            int e   = idx & (H_ - 1);
            g_hbuf[par][e][0] = par
                ? ((unsigned long long)__float_as_uint(h0[e]) << 32)
                : 0xFFFFFFFFull;
        }
    }

    const int bm = blockIdx.y * 64;
    const int bn = blockIdx.x * 64;
    const int tx = tid & 15, ty = tid >> 4;

    const int aRow = tid >> 2;            // 0..63
    const int aK   = (tid & 3) << 2;      // 0,4,8,12
    const int bRow = tid >> 4;            // 0..15
    const int bCol = (tid & 15) << 2;     // 0..60

    const float* Aptr = A + (size_t)(bm + aRow) * K + aK;
    const float* Bptr = B + (size_t)bRow * N + bn + bCol;

    float acc[4][4];
#pragma unroll
    for (int i = 0; i < 4; i++)
#pragma unroll
        for (int j = 0; j < 4; j++) acc[i][j] = 0.f;

    for (int k0 = 0; k0 < K; k0 += 16) {
        float4 a4 = *(const float4*)(Aptr + k0);
        float4 b4 = *(const float4*)(Bptr + (size_t)k0 * N);
        As[aK + 0][aRow] = a4.x;
        As[aK + 1][aRow] = a4.y;
        As[aK + 2][aRow] = a4.z;
        As[aK + 3][aRow] = a4.w;
        *(float4*)&Bs[bRow][bCol] = b4;
        __syncthreads();
#pragma unroll
        for (int k = 0; k < 16; k++) {
            float4 av = *(const float4*)&As[k][ty << 2];
            float4 bv = *(const float4*)&Bs[k][tx << 2];
            float a_[4] = {av.x, av.y, av.z, av.w};
            float b_[4] = {bv.x, bv.y, bv.z, bv.w};
#pragma unroll
            for (int i = 0; i < 4; i++)
#pragma unroll
                for (int j = 0; j < 4; j++)
                    acc[i][j] = fmaf(a_[i], b_[j], acc[i][j]);
        }
        __syncthreads();
    }

#pragma unroll
    for (int i = 0; i < 4; i++) {
        int m = bm + (ty << 2) + i;
#pragma unroll
        for (int j = 0; j < 4; j++) {
            int n = bn + (tx << 2) + j;
            float v = acc[i][j] + bias[n];
            if (doRelu) v = fmaxf(v, 0.f);
            C[(size_t)m * N + n] = v;
        }
    }
}

// ---------------- GRU recurrence: 64 persistent CTAs ------------------------
// Tagged-word sync, one 128B line per element. Warp 0 alone polls (done-mask
// sweep), stages to shared, one __syncthreads releases the CTA. Next-step X
// rows are prefetched right after detection (full-step DRAM cover). Producer
// issues the tagged h store FIRST, bookkeeping after.
__global__ __launch_bounds__(256) void recur_kernel(
    const float* __restrict__ Ug,    // [H, 3H] row-major
    const float* __restrict__ brec,  // [3H]  (bg row 1)
    const float* __restrict__ X,     // [T, 3H]
    float* __restrict__ seq,         // [T, H]
    float* __restrict__ hT_out)      // [H]
{
    __shared__ float sh[2][H_];
    const int tid  = threadIdx.x;
    const int lane = tid & 31;
    const int w    = tid >> 5;                 // warp 0..7
    const int j    = blockIdx.x * HC + w;      // hidden unit owned by this warp

    // Stage this warp's Ug columns into registers: lane covers k = lane+32*kk
    float wz[16], wr[16], wh[16];
#pragma unroll
    for (int kk = 0; kk < 16; kk++) {
        const float* row = Ug + (size_t)(lane + (kk << 5)) * H3_;
        wz[kk] = row[j];
        wr[kk] = row[j + H_];
        wh[kk] = row[j + 2 * H_];
    }
    const float bz = brec[j], br = brec[j + H_], bh = brec[j + 2 * H_];

    // lane 0 holds the X row values for this unit; prefetched one step ahead
    float xz = 0.f, xr = 0.f, xh = 0.f;
    if (lane == 0) { xz = X[j]; xr = X[j + H_]; xh = X[j + 2 * H_]; }

    // poll warp: lane handles elements e = lane + 32*i; skip own CTA's 8 (t>0)
    unsigned ownMask = 0;
    {
        int base = blockIdx.x * HC;
#pragma unroll
        for (int i = 0; i < 16; i++) {
            int e = lane + (i << 5);
            if (e >= base && e < base + HC) ownMask |= (1u << i);
        }
    }

    for (int t = 0; t < T_; t++) {
        const int p = t & 1;
        const unsigned tag = (unsigned)t;

        if (w == 0) {
            const unsigned long long (*rb)[EPAD] = g_hbuf[(t - 1) & 1];
            unsigned pend = 0xFFFFu;
            if (t > 0) pend &= ~ownMask;      // own values already staged
            unsigned long long v[16];
            while (pend) {
                unsigned np = pend;
#pragma unroll
                for (int i = 0; i < 16; i++) {
                    if (pend & (1u << i)) {
                        unsigned long long x = ld_relaxed_u64(&rb[lane + (i << 5)][0]);
                        if ((unsigned)x == tag) { v[i] = x; np &= ~(1u << i); }
                    }
                }
                pend = np;
            }
            unsigned todo = 0xFFFFu;
            if (t > 0) todo &= ~ownMask;
#pragma unroll
            for (int i = 0; i < 16; i++)
                if (todo & (1u << i))
                    sh[p][lane + (i << 5)] = __uint_as_float((unsigned)(v[i] >> 32));
        }
        __syncthreads();

        // prefetch NEXT step's X row now: ~full step of latency cover for DRAM
        float nxz = 0.f, nxr = 0.f, nxh = 0.f;
        if (lane == 0 && t + 1 < T_) {
            const float* xp = X + (size_t)(t + 1) * H3_;
            nxz = __ldcs(xp + j); nxr = __ldcs(xp + j + H_); nxh = __ldcs(xp + j + 2 * H_);
        }

        // rec dot products: 3 gates, 16 k's per lane (2 accumulators per gate)
        float az0 = 0.f, ar0 = 0.f, ah0 = 0.f;
        float az1 = 0.f, ar1 = 0.f, ah1 = 0.f;
#pragma unroll
        for (int kk = 0; kk < 16; kk += 2) {
            float h0v = sh[p][lane + (kk << 5)];
            float h1v = sh[p][lane + ((kk + 1) << 5)];
            az0 = fmaf(h0v, wz[kk], az0);   az1 = fmaf(h1v, wz[kk + 1], az1);
            ar0 = fmaf(h0v, wr[kk], ar0);   ar1 = fmaf(h1v, wr[kk + 1], ar1);
            ah0 = fmaf(h0v, wh[kk], ah0);   ah1 = fmaf(h1v, wh[kk + 1], ah1);
        }
        float az = az0 + az1, ar = ar0 + ar1, ah = ah0 + ah1;
#pragma unroll
        for (int off = 16; off; off >>= 1) {
            az += __shfl_xor_sync(0xffffffffu, az, off);
            ar += __shfl_xor_sync(0xffffffffu, ar, off);
            ah += __shfl_xor_sync(0xffffffffu, ah, off);
        }

        if (lane == 0) {
            float zt = __fdividef(1.f, 1.f + __expf(-(xz + az + bz)));
            float rt = __fdividef(1.f, 1.f + __expf(-(xr + ar + br)));
            float hh = __fdividef(1.f, 1.f + __expf(-(xh + rt * (ah + bh))));
            float hp = sh[p][j];
            float hn = fmaf(zt, hp - hh, hh);   // zt*hp + (1-zt)*hh
            // critical store FIRST
            unsigned long long pk =
                ((unsigned long long)__float_as_uint(hn) << 32) | (unsigned)(t + 1);
            st_relaxed_u64(&g_hbuf[p][j][0], pk);
            // bookkeeping after
            sh[p ^ 1][j] = hn;
            seq[(size_t)t * H_ + j] = hn;
            if (t == T_ - 1) hT_out[j] = hn;
            xz = nxz; xr = nxr; xh = nxh;
        }
        // single barrier per step: sh parity double-buffered (see R2 notes)
    }
}

// ---------------- heads: softmax policy (18) + value, one warp per row -----
__global__ __launch_bounds__(256) void head_kernel(
    const float* __restrict__ seq, const float* __restrict__ Wp,
    const float* __restrict__ bp,  const float* __restrict__ Wv,
    const float* __restrict__ bv,  float* __restrict__ out)
{
    int row  = blockIdx.x * (blockDim.x >> 5) + (threadIdx.x >> 5);
    int lane = threadIdx.x & 31;
    if (row >= T_) return;
    const float* h = seq + (size_t)row * H_;

    const float* wcol = (lane < 18) ? (Wp + lane) : Wv;
    const int stride  = (lane < 18) ? A_ : 1;
    float acc = 0.f;
    if (lane < 19) {
#pragma unroll 8
        for (int k = 0; k < H_; k++)
            acc = fmaf(__ldg(h + k), __ldg(wcol + k * stride), acc);
    }

    const float NEG_INF = __int_as_float(0xff800000);
    float logit = (lane < 18) ? acc + bp[lane] : NEG_INF;
    float m = logit;
#pragma unroll
    for (int off = 16; off; off >>= 1)
        m = fmaxf(m, __shfl_xor_sync(0xffffffffu, m, off));
    float e = (lane < 18) ? __expf(logit - m) : 0.f;
    float s = e;
#pragma unroll
    for (int off = 16; off; off >>= 1)
        s += __shfl_xor_sync(0xffffffffu, s, off);

    if (lane < 18)  out[(size_t)row * A_ + lane] = e / s;
    if (lane == 18) out[(size_t)T_ * A_ + row]   = acc + bv[0];
}

// ---------------- launch --------------------------------------------------
extern "C" void kernel_launch(void* const* d_in, const int* in_sizes, int n_in,
                              void* d_out, int out_size)
{
    (void)in_sizes; (void)n_in; (void)out_size;
    const float* x  = (const float*)d_in[0];
    const float* h0 = (const float*)d_in[1];
    const float* W1 = (const float*)d_in[2];
    const float* b1 = (const float*)d_in[3];
    const float* W2 = (const float*)d_in[4];
    const float* b2 = (const float*)d_in[5];
    const float* Wg = (const float*)d_in[6];
    const float* Ug = (const float*)d_in[7];
    const float* bg = (const float*)d_in[8];
    const float* Wp = (const float*)d_in[9];
    const float* bp = (const float*)d_in[10];
    const float* Wv = (const float*)d_in[11];
    const float* bv = (const float*)d_in[12];
    float* out = (float*)d_out;

    float *z1p, *z2p, *Xp, *seqp;
    cudaGetSymbolAddress((void**)&z1p,  g_z1);
    cudaGetSymbolAddress((void**)&z2p,  g_z2);
    cudaGetSymbolAddress((void**)&Xp,   g_X);
    cudaGetSymbolAddress((void**)&seqp, g_seq);

    gemm_kernel<<<dim3(D_ / 64,  T_ / 64), 256>>>(x,   W1, b1, z1p, T_, D_,  DIN, 1, h0, 1);
    gemm_kernel<<<dim3(D_ / 64,  T_ / 64), 256>>>(z1p, W2, b2, z2p, T_, D_,  D_,  1, h0, 0);
    gemm_kernel<<<dim3(H3_ / 64, T_ / 64), 256>>>(z2p, Wg, bg, Xp,  T_, H3_, D_,  0, h0, 0);
    recur_kernel<<<NC, 256>>>(Ug, bg + H3_, Xp, seqp, out + (size_t)T_ * A_ + T_);
    head_kernel<<<T_ / 8, 256>>>(seqp, Wp, bp, Wv, bv, out);
}

// round 8
// speedup vs baseline: 1.8144x; 1.8144x over previous
#include <cuda_runtime.h>
#include <math.h>

#define T_   8192
#define DIN  2048
#define D_   512
#define H_   512
#define H3_  1536
#define A_   18

#define CLN  16          // cluster size: 16 CTAs, one cluster, 32 units each

// ---------------- scratch (device globals: no allocation allowed) ----------
__device__ float g_z1[(size_t)T_ * D_];          // 16 MB
__device__ float g_z2[(size_t)T_ * D_];          // 16 MB
__device__ float g_X [(size_t)T_ * H3_];         // 48 MB
__device__ float g_seq[(size_t)T_ * H_];         // 16 MB

// ---------------- fp32 tiled GEMM: C = act(A[M,K] @ B[K,N] + bias) ---------
__global__ __launch_bounds__(256) void gemm_kernel(
    const float* __restrict__ A, const float* __restrict__ B,
    const float* __restrict__ bias, float* __restrict__ C,
    int M, int N, int K, int doRelu)
{
    __shared__ float As[16][64];
    __shared__ float Bs[16][64];
    const int tid = threadIdx.x;
    const int bm = blockIdx.y * 64;
    const int bn = blockIdx.x * 64;
    const int tx = tid & 15, ty = tid >> 4;

    const int aRow = tid >> 2;            // 0..63
    const int aK   = (tid & 3) << 2;      // 0,4,8,12
    const int bRow = tid >> 4;            // 0..15
    const int bCol = (tid & 15) << 2;     // 0..60

    const float* Aptr = A + (size_t)(bm + aRow) * K + aK;
    const float* Bptr = B + (size_t)bRow * N + bn + bCol;

    float acc[4][4];
#pragma unroll
    for (int i = 0; i < 4; i++)
#pragma unroll
        for (int j = 0; j < 4; j++) acc[i][j] = 0.f;

    for (int k0 = 0; k0 < K; k0 += 16) {
        float4 a4 = *(const float4*)(Aptr + k0);
        float4 b4 = *(const float4*)(Bptr + (size_t)k0 * N);
        As[aK + 0][aRow] = a4.x;
        As[aK + 1][aRow] = a4.y;
        As[aK + 2][aRow] = a4.z;
        As[aK + 3][aRow] = a4.w;
        *(float4*)&Bs[bRow][bCol] = b4;
        __syncthreads();
#pragma unroll
        for (int k = 0; k < 16; k++) {
            float4 av = *(const float4*)&As[k][ty << 2];
            float4 bv = *(const float4*)&Bs[k][tx << 2];
            float a_[4] = {av.x, av.y, av.z, av.w};
            float b_[4] = {bv.x, bv.y, bv.z, bv.w};
#pragma unroll
            for (int i = 0; i < 4; i++)
#pragma unroll
                for (int j = 0; j < 4; j++)
                    acc[i][j] = fmaf(a_[i], b_[j], acc[i][j]);
        }
        __syncthreads();
    }

#pragma unroll
    for (int i = 0; i < 4; i++) {
        int m = bm + (ty << 2) + i;
#pragma unroll
        for (int j = 0; j < 4; j++) {
            int n = bn + (tx << 2) + j;
            float v = acc[i][j] + bias[n];
            if (doRelu) v = fmaxf(v, 0.f);
            C[(size_t)m * N + n] = v;
        }
    }
}

// ---------------- GRU recurrence: ONE cluster of 16 CTAs --------------------
// No L2 sync at all. Hardware cluster barrier (one per step, parity double-
// buffered smem h), DSMEM peer reads of h pairs, f32x2 packed FMA dots.
__global__ void __cluster_dims__(CLN, 1, 1) __launch_bounds__(256, 1)
recur_kernel(
    const float* __restrict__ Ug,    // [H, 3H] row-major
    const float* __restrict__ brec,  // [3H]  (bg row 1)
    const float* __restrict__ X,     // [T, 3H]
    float* __restrict__ seq,         // [T, H]
    float* __restrict__ hT_out,      // [H]
    const float* __restrict__ h0)    // [H]
{
    __shared__ __align__(16) float hbuf[2][32];   // own 32 units, parity-buffered
    const int tid  = threadIdx.x;
    const int lane = tid & 31;
    const int w    = tid >> 5;                    // warp 0..7
    unsigned rank;
    asm("mov.u32 %0, %%cluster_ctarank;" : "=r"(rank));
    const int jb = (int)rank * 32 + w * 4;        // warp's first global unit
    const int j  = jb + lane;                     // valid for lane<4 (gate lane)

    // ---- stage Ug slice as packed f32x2: wv[u*3+g][i], pair p = lane+32*i ----
    unsigned long long wv[12][8];
#pragma unroll
    for (int i = 0; i < 8; i++) {
        const int p  = lane + (i << 5);
        const float* r0 = Ug + (size_t)(2 * p) * H3_;
        const float* r1 = r0 + H3_;
#pragma unroll
        for (int u = 0; u < 4; u++)
#pragma unroll
            for (int g = 0; g < 3; g++) {
                const int col = jb + u + g * H_;
                float lo = r0[col], hi = r1[col];
                asm("mov.b64 %0, {%1, %2};"
                    : "=l"(wv[u * 3 + g][i]) : "f"(lo), "f"(hi));
            }
    }

    // ---- DSMEM addresses for my 8 h-pairs (parity-0 base; +128B for par 1) --
    unsigned ra[8];
    {
        unsigned lb;
        asm("{ .reg .u64 t; cvta.to.shared.u64 t, %1; cvt.u32.u64 %0, t; }"
            : "=r"(lb) : "l"((const void*)&hbuf[0][0]));
#pragma unroll
        for (int i = 0; i < 8; i++) {
            const int p = lane + (i << 5);
            unsigned la = lb + ((p & 15) << 3);      // float2 within hbuf[0]
            unsigned rr = (unsigned)(p >> 4);        // source CTA rank
            asm("mapa.shared::cluster.u32 %0, %1, %2;"
                : "=r"(ra[i]) : "r"(la), "r"(rr));
        }
    }

    // ---- per-unit constants + first X row + h_{-1} (lane<4 only) ------------
    float bz = 0.f, brr = 0.f, bh = 0.f, xz = 0.f, xr = 0.f, xh = 0.f;
    if (lane < 4) {
        bz = brec[j]; brr = brec[j + H_]; bh = brec[j + 2 * H_];
        xz = X[j];    xr = X[j + H_];     xh = X[j + 2 * H_];
        hbuf[1][w * 4 + lane] = h0[j];    // t=0 reads parity (0-1)&1 = 1
    }
    asm volatile("barrier.cluster.arrive.aligned;" ::: "memory");

    for (int t = 0; t < T_; t++) {
        asm volatile("barrier.cluster.wait.aligned;" ::: "memory");
        const int q = (t - 1) & 1;
        const int p = t & 1;

        // DSMEM loads of h_{t-1} pairs (MLP 8)
        unsigned long long hv[8];
#pragma unroll
        for (int i = 0; i < 8; i++)
            asm volatile("ld.shared::cluster.u64 %0, [%1];"
                         : "=l"(hv[i]) : "r"(ra[i] + (unsigned)(q << 7)));

        // prefetch next step's X row (covered by this step's compute)
        float nxz = 0.f, nxr = 0.f, nxh = 0.f;
        if (lane < 4 && t + 1 < T_) {
            const float* xp = X + (size_t)(t + 1) * H3_;
            nxz = __ldcs(xp + j); nxr = __ldcs(xp + j + H_); nxh = __ldcs(xp + j + 2 * H_);
        }

        // packed dot products: 12 outputs (4 units x 3 gates), 8 pairs each
        unsigned long long acc[12];
#pragma unroll
        for (int c = 0; c < 12; c++) acc[c] = 0ull;
#pragma unroll
        for (int i = 0; i < 8; i++)
#pragma unroll
            for (int c = 0; c < 12; c++)
                asm("fma.rn.f32x2 %0, %1, %2, %3;"
                    : "=l"(acc[c]) : "l"(hv[i]), "l"(wv[c][i]), "l"(acc[c]));

        float s[12];
#pragma unroll
        for (int c = 0; c < 12; c++) {
            float lo, hi;
            asm("mov.b64 {%0, %1}, %2;" : "=f"(lo), "=f"(hi) : "l"(acc[c]));
            s[c] = lo + hi;
        }
#pragma unroll
        for (int off = 16; off; off >>= 1)
#pragma unroll
            for (int c = 0; c < 12; c++)
                s[c] += __shfl_xor_sync(0xffffffffu, s[c], off);

        // lanes 0..3 finish their unit's gates in parallel
        if (lane < 4) {
            const int ul = w * 4 + lane;
            float zt = __fdividef(1.f, 1.f + __expf(-(xz + s[lane * 3 + 0] + bz)));
            float rt = __fdividef(1.f, 1.f + __expf(-(xr + s[lane * 3 + 1] + brr)));
            float hh = __fdividef(1.f, 1.f + __expf(-(xh + rt * (s[lane * 3 + 2] + bh))));
            float hp = hbuf[q][ul];
            float hn = fmaf(zt, hp - hh, hh);     // zt*hp + (1-zt)*hh
            hbuf[p][ul] = hn;
            seq[(size_t)t * H_ + j] = hn;
            if (t == T_ - 1) hT_out[j] = hn;
            xz = nxz; xr = nxr; xh = nxh;
        }
        asm volatile("barrier.cluster.arrive.aligned;" ::: "memory");
        // parity double-buffer => one barrier/step: parity p is only re-written
        // at step t+2, whose wait orders it after ALL step-(t+1) reads of h_t.
    }
    asm volatile("barrier.cluster.wait.aligned;" ::: "memory");
}

// ---------------- heads: softmax policy (18) + value, one warp per row -----
__global__ __launch_bounds__(256) void head_kernel(
    const float* __restrict__ seq, const float* __restrict__ Wp,
    const float* __restrict__ bp,  const float* __restrict__ Wv,
    const float* __restrict__ bv,  float* __restrict__ out)
{
    int row  = blockIdx.x * (blockDim.x >> 5) + (threadIdx.x >> 5);
    int lane = threadIdx.x & 31;
    if (row >= T_) return;
    const float* h = seq + (size_t)row * H_;

    const float* wcol = (lane < 18) ? (Wp + lane) : Wv;
    const int stride  = (lane < 18) ? A_ : 1;
    float acc = 0.f;
    if (lane < 19) {
#pragma unroll 8
        for (int k = 0; k < H_; k++)
            acc = fmaf(__ldg(h + k), __ldg(wcol + k * stride), acc);
    }

    const float NEG_INF = __int_as_float(0xff800000);
    float logit = (lane < 18) ? acc + bp[lane] : NEG_INF;
    float m = logit;
#pragma unroll
    for (int off = 16; off; off >>= 1)
        m = fmaxf(m, __shfl_xor_sync(0xffffffffu, m, off));
    float e = (lane < 18) ? __expf(logit - m) : 0.f;
    float s = e;
#pragma unroll
    for (int off = 16; off; off >>= 1)
        s += __shfl_xor_sync(0xffffffffu, s, off);

    if (lane < 18)  out[(size_t)row * A_ + lane] = e / s;
    if (lane == 18) out[(size_t)T_ * A_ + row]   = acc + bv[0];
}

// ---------------- launch --------------------------------------------------
extern "C" void kernel_launch(void* const* d_in, const int* in_sizes, int n_in,
                              void* d_out, int out_size)
{
    (void)in_sizes; (void)n_in; (void)out_size;
    const float* x  = (const float*)d_in[0];
    const float* h0 = (const float*)d_in[1];
    const float* W1 = (const float*)d_in[2];
    const float* b1 = (const float*)d_in[3];
    const float* W2 = (const float*)d_in[4];
    const float* b2 = (const float*)d_in[5];
    const float* Wg = (const float*)d_in[6];
    const float* Ug = (const float*)d_in[7];
    const float* bg = (const float*)d_in[8];
    const float* Wp = (const float*)d_in[9];
    const float* bp = (const float*)d_in[10];
    const float* Wv = (const float*)d_in[11];
    const float* bv = (const float*)d_in[12];
    float* out = (float*)d_out;

    float *z1p, *z2p, *Xp, *seqp;
    cudaGetSymbolAddress((void**)&z1p,  g_z1);
    cudaGetSymbolAddress((void**)&z2p,  g_z2);
    cudaGetSymbolAddress((void**)&Xp,   g_X);
    cudaGetSymbolAddress((void**)&seqp, g_seq);

    // 16-CTA cluster needs the nonportable-size opt-in (idempotent, cheap)
    static int attrSet = 0;
    if (!attrSet) {
        cudaFuncSetAttribute(recur_kernel,
                             cudaFuncAttributeNonPortableClusterSizeAllowed, 1);
        attrSet = 1;
    }

    gemm_kernel<<<dim3(D_ / 64,  T_ / 64), 256>>>(x,   W1, b1, z1p, T_, D_,  DIN, 1);
    gemm_kernel<<<dim3(D_ / 64,  T_ / 64), 256>>>(z1p, W2, b2, z2p, T_, D_,  D_,  1);
    gemm_kernel<<<dim3(H3_ / 64, T_ / 64), 256>>>(z2p, Wg, bg, Xp,  T_, H3_, D_,  0);
    recur_kernel<<<CLN, 256>>>(Ug, bg + H3_, Xp, seqp,
                               out + (size_t)T_ * A_ + T_, h0);
    head_kernel<<<T_ / 8, 256>>>(seqp, Wp, bp, Wv, bv, out);
}